// round 14
// baseline (speedup 1.0000x reference)
#include <cuda_runtime.h>
#include <cstdint>

// ExtractLearnableSlices — TMA loads + vectorized LDS.128 epilogue.
//   x: (B=64, C=64, L=16384) f32
//   channel_params/offset_params: (128,) f32
//   out: (B=64, N=128, W=512) f32
//
// l0 = pf0 & ~3 (16B-aligned TMA source), d = pf0-l0 in {0..3} uniform per
// head. Thread with j0 = 4*tlo needs window elems d+j0 .. d+j0+4, all inside
// floats [j0, j0+7] = two LDS.128. Epilogue per 4 outputs: 4 LDS.128 +
// 1 STG.128 (vs 16 LDS.32 + 4 STG.32). switch(d) keeps selection static.
// Time lerp = signed chord at pos = fl(t0+j) vs assumed floor pf0+j (R10
// math, passed at rel_err 4.9e-4).

#define B_DIM   64
#define C_DIM   64
#define L_DIM   16384
#define N_HEADS 128
#define WIDTH   512
#define THREADS 256
#define NB      8                   // batches per block
#define NPHASE  4                   // 2 batches per phase
#define WIN     520                 // floats per window
#define WIN_B   (WIN * 4)           // 2080 bytes, multiple of 16

__device__ __forceinline__ uint32_t smem_u32(const void* p) {
    uint64_t t;
    asm("cvta.to.shared.u64 %0, %1;" : "=l"(t) : "l"(p));
    return (uint32_t)t;
}

__device__ __forceinline__ void mbar_wait_acq(uint32_t addr) {
    uint32_t done;
    asm volatile(
        "{\n\t.reg .pred p;\n\t"
        "mbarrier.try_wait.parity.acquire.cta.shared::cta.b64 p, [%1], 0;\n\t"
        "selp.b32 %0, 1, 0, p;\n\t}"
        : "=r"(done) : "r"(addr) : "memory");
    while (!done) {
        asm volatile(
            "{\n\t.reg .pred p;\n\t"
            "mbarrier.try_wait.parity.acquire.cta.shared::cta.b64 p, [%1], 0, 0x989680;\n\t"
            "selp.b32 %0, 1, 0, p;\n\t}"
            : "=r"(done) : "r"(addr) : "memory");
    }
}

template<int E>
__device__ __forceinline__ float elem(const float4& A, const float4& B) {
    if constexpr (E == 0) return A.x;
    else if constexpr (E == 1) return A.y;
    else if constexpr (E == 2) return A.z;
    else if constexpr (E == 3) return A.w;
    else if constexpr (E == 4) return B.x;
    else if constexpr (E == 5) return B.y;
    else if constexpr (E == 6) return B.z;
    else return B.w;
}

// Shared windows + barriers
struct Smem {
    float win[NB][2][WIN];          // [batch][floor/ceil channel][window]
    uint64_t mbar[NPHASE];
};

template<int D>
__device__ __forceinline__ float4 quad_out(
    const float4& fA, const float4& fB, const float4& cA, const float4& cB,
    float wc, const float* wt)
{
    const float a0 = elem<D + 0>(fA, fB), c0 = elem<D + 0>(cA, cB);
    const float a1 = elem<D + 1>(fA, fB), c1 = elem<D + 1>(cA, cB);
    const float a2 = elem<D + 2>(fA, fB), c2 = elem<D + 2>(cA, cB);
    const float a3 = elem<D + 3>(fA, fB), c3 = elem<D + 3>(cA, cB);
    const float a4 = elem<D + 4>(fA, fB), c4 = elem<D + 4>(cA, cB);

    const float v0 = a0 + wc * (c0 - a0);
    const float v1 = a1 + wc * (c1 - a1);
    const float v2 = a2 + wc * (c2 - a2);
    const float v3 = a3 + wc * (c3 - a3);
    const float v4 = a4 + wc * (c4 - a4);

    float4 o;
    o.x = v0 + wt[0] * (v1 - v0);
    o.y = v1 + wt[1] * (v2 - v1);
    o.z = v2 + wt[2] * (v3 - v2);
    o.w = v3 + wt[3] * (v4 - v3);
    return o;
}

template<int D>
__device__ __forceinline__ void run_phases(
    Smem* sm, const uint32_t* mb, float* __restrict__ obase, size_t ostride,
    float wc, const float* wt, int tlo, int bsel)
{
    #pragma unroll
    for (int p = 0; p < NPHASE; ++p) {
        mbar_wait_acq(mb[p]);
        const int bb = 2 * p + bsel;
        const float4* __restrict__ wf4 = (const float4*)sm->win[bb][0];
        const float4* __restrict__ wc4 = (const float4*)sm->win[bb][1];
        const float4 fA = wf4[tlo];
        const float4 fB = wf4[tlo + 1];
        const float4 cA = wc4[tlo];
        const float4 cB = wc4[tlo + 1];
        *(float4*)(obase + bb * ostride) = quad_out<D>(fA, fB, cA, cB, wc, wt);
    }
}

__global__ __launch_bounds__(THREADS) void extract_slices_kernel(
    const float* __restrict__ x,
    const float* __restrict__ channel_params,
    const float* __restrict__ offset_params,
    float* __restrict__ out)
{
    __shared__ __align__(16) Smem sm;

    const int tid  = threadIdx.x;       // 0..255
    const int tlo  = tid & 127;         // j0 = 4*tlo
    const int bsel = tid >> 7;          // batch-in-phase 0/1
    const int i    = blockIdx.x;        // head
    const int b0   = blockIdx.y * NB;   // first batch

    uint32_t mb[NPHASE];
    #pragma unroll
    for (int p = 0; p < NPHASE; ++p) mb[p] = smem_u32(&sm.mbar[p]);

    if (tid == 0) {
        #pragma unroll
        for (int p = 0; p < NPHASE; ++p)
            asm volatile("mbarrier.init.shared.b64 [%0], 1;" :: "r"(mb[p]) : "memory");
    }
    __syncthreads();

    // ---- per-head params (same math as all passing rounds) ----
    const float cp = __ldg(&channel_params[i]);
    const float op = __ldg(&offset_params[i]);

    const float sc      = 1.0f / (1.0f + expf(-cp));
    const float desired = sc * (float)(C_DIM - 1);   // > 0
    const int   fc      = (int)desired;              // floor (positive)
    const int   cc      = min(fc + 1, C_DIM - 1);
    const float wc      = desired - (float)fc;

    const float so  = 1.0f / (1.0f + expf(-op));
    const float t0  = so * (float)(L_DIM - WIDTH);   // > 0
    const int   pf0 = (int)t0;                       // floor (positive)
    const int   l0  = pf0 & ~3;                      // 16B-aligned origin
    const int   d   = pf0 - l0;                      // 0..3, uniform per head

    const int xfo = fc * L_DIM + l0;
    const int xco = cc * L_DIM + l0;

    // ---- issue all 16 bulk copies (2 batches per phase, in phase order) ----
    if (tid == 0) {
        #pragma unroll
        for (int p = 0; p < NPHASE; ++p)
            asm volatile("mbarrier.arrive.expect_tx.shared.b64 _, [%0], %1;"
                         :: "r"(mb[p]), "r"((uint32_t)(2 * 2 * WIN_B)) : "memory");
        #pragma unroll
        for (int bb = 0; bb < NB; ++bb) {
            const uint32_t m = mb[bb >> 1];
            const size_t base = (size_t)(b0 + bb) * (size_t)(C_DIM * L_DIM);
            const float* srcf = x + base + xfo;
            const float* srcc = x + base + xco;
            const uint32_t df = smem_u32(&sm.win[bb][0][0]);
            const uint32_t dc = smem_u32(&sm.win[bb][1][0]);
            asm volatile(
                "cp.async.bulk.shared::cta.global.mbarrier::complete_tx::bytes "
                "[%0], [%1], %2, [%3];"
                :: "r"(df), "l"(srcf), "r"((uint32_t)WIN_B), "r"(m) : "memory");
            asm volatile(
                "cp.async.bulk.shared::cta.global.mbarrier::complete_tx::bytes "
                "[%0], [%1], %2, [%3];"
                :: "r"(dc), "l"(srcc), "r"((uint32_t)WIN_B), "r"(m) : "memory");
        }
    }

    // ---- hoisted: signed chord weights vs assumed floor pf0 + j ----
    const int j0 = 4 * tlo;
    float wt[4];
    #pragma unroll
    for (int m = 0; m < 4; ++m) {
        const float pos = t0 + (float)(j0 + m);      // exact ref f32 math
        wt[m] = pos - (float)(pf0 + j0 + m);         // signed chord weight
    }

    const size_t ostride = (size_t)N_HEADS * WIDTH;
    float* __restrict__ obase = out + ((size_t)b0 * N_HEADS + i) * WIDTH + j0;

    switch (d) {   // uniform per block
        case 0:  run_phases<0>(&sm, mb, obase, ostride, wc, wt, tlo, bsel); break;
        case 1:  run_phases<1>(&sm, mb, obase, ostride, wc, wt, tlo, bsel); break;
        case 2:  run_phases<2>(&sm, mb, obase, ostride, wc, wt, tlo, bsel); break;
        default: run_phases<3>(&sm, mb, obase, ostride, wc, wt, tlo, bsel); break;
    }
}

extern "C" void kernel_launch(void* const* d_in, const int* in_sizes, int n_in,
                              void* d_out, int out_size)
{
    const float* x  = (const float*)d_in[0];
    const float* ch = (const float*)d_in[1];
    const float* of = (const float*)d_in[2];
    float* out = (float*)d_out;

    dim3 grid(N_HEADS, B_DIM / NB);
    extract_slices_kernel<<<grid, THREADS>>>(x, ch, of, out);
}